// round 1
// baseline (speedup 1.0000x reference)
#include <cuda_runtime.h>
#include <cstdint>

// PPEG: out[b, 0, c]   = x[b, 0, c]                       (cls token)
//       out[b, 1+p, c] = combined 7x7 depthwise conv of the 64x64 map
// Combined weights: w_eff[c][ky][kx] = w7 + (w5 inner 5x5) + (w3 inner 3x3) + 1@center
// Combined bias:    b7 + b5 + b3
//
// Layout facts: x is (16, 4097, 512) float32, channel-last. H=W=64.

#define CH   512
#define HW   64
#define NTOK 4097

__device__ float g_weff[49 * CH];   // [tap][channel], tap-major for coalesced lane loads
__device__ float g_bsum[CH];

// ---------------------------------------------------------------------------
// packed f32x2 FMA (sm_103a FFMA2 — only reachable via PTX)
__device__ __forceinline__ unsigned long long ffma2(unsigned long long a,
                                                    unsigned long long b,
                                                    unsigned long long c) {
    unsigned long long d;
    asm("fma.rn.f32x2 %0, %1, %2, %3;" : "=l"(d) : "l"(a), "l"(b), "l"(c));
    return d;
}

// ---------------------------------------------------------------------------
// Kernel 1: fold w7/w5/w3/identity into one 7x7 weight set + summed bias
__global__ void ppeg_prep(const float* __restrict__ w7, const float* __restrict__ b7,
                          const float* __restrict__ w5, const float* __restrict__ b5,
                          const float* __restrict__ w3, const float* __restrict__ b3) {
    int c = threadIdx.x;           // one thread per channel, 512 threads
    g_bsum[c] = b7[c] + b5[c] + b3[c];
    #pragma unroll
    for (int ky = 0; ky < 7; ++ky) {
        #pragma unroll
        for (int kx = 0; kx < 7; ++kx) {
            float v = w7[c * 49 + ky * 7 + kx];
            if (ky >= 1 && ky <= 5 && kx >= 1 && kx <= 5)
                v += w5[c * 25 + (ky - 1) * 5 + (kx - 1)];
            if (ky >= 2 && ky <= 4 && kx >= 2 && kx <= 4)
                v += w3[c * 9 + (ky - 2) * 3 + (kx - 2)];
            if (ky == 3 && kx == 3)
                v += 1.0f;                          // identity (residual) term
            g_weff[(ky * 7 + kx) * CH + c] = v;
        }
    }
}

// ---------------------------------------------------------------------------
// Kernel 2: cls-token passthrough
__global__ void ppeg_cls(const float* __restrict__ x, float* __restrict__ out) {
    size_t off = (size_t)blockIdx.x * NTOK * CH + threadIdx.x;
    out[off] = x[off];
}

// ---------------------------------------------------------------------------
// Kernel 3: combined 7x7 depthwise conv.
//   lane   = channel pair (64 channels per block, lane*2 offset) -> 256B coalesced
//   warp   = 8x2 output pixel subtile
//   block  = 4 warps (2x2) -> 16x4 pixel tile, 64 channels
//   grid   = (4 xtiles, 16 ytiles, 16 batch * 8 channel groups)
__global__ void __launch_bounds__(128)
ppeg_conv(const float* __restrict__ x, float* __restrict__ out) {
    const int lane = threadIdx.x & 31;
    const int warp = threadIdx.x >> 5;
    const int wx = warp & 1;
    const int wy = warp >> 1;
    const int x0 = blockIdx.x * 16 + wx * 8;   // 8 output cols per thread (RX=8)
    const int y0 = blockIdx.y * 4 + wy * 2;    // 2 output rows per thread (RY=2)
    const int b  = blockIdx.z >> 3;
    const int cg = blockIdx.z & 7;
    const int c  = cg * 64 + lane * 2;

    // 49 combined weights for this channel pair (kept in registers)
    unsigned long long w[49];
    #pragma unroll
    for (int t = 0; t < 49; ++t)
        w[t] = *reinterpret_cast<const unsigned long long*>(&g_weff[t * CH + c]);
    const unsigned long long bias =
        *reinterpret_cast<const unsigned long long*>(&g_bsum[c]);

    unsigned long long acc[2][8];
    #pragma unroll
    for (int ry = 0; ry < 2; ++ry)
        #pragma unroll
        for (int rx = 0; rx < 8; ++rx)
            acc[ry][rx] = bias;

    const float* xb = x + ((size_t)b * NTOK + 1) * CH + c;

    // Sliding row window: 8 input rows feed the 2 output rows (RY+6).
    #pragma unroll
    for (int riy = 0; riy < 8; ++riy) {
        const int iy = y0 - 3 + riy;
        const bool yok = ((unsigned)iy < (unsigned)HW);
        const float* row = xb + (size_t)iy * HW * CH;

        unsigned long long rw[14];
        #pragma unroll
        for (int i = 0; i < 14; ++i) {
            const int xc = x0 - 3 + i;
            rw[i] = (yok && (unsigned)xc < (unsigned)HW)
                  ? *reinterpret_cast<const unsigned long long*>(&row[(size_t)xc * CH])
                  : 0ULL;
        }

        #pragma unroll
        for (int ky = 0; ky < 7; ++ky) {
            const int ry = riy - ky;          // compile-time after full unroll
            if (ry == 0 || ry == 1) {
                #pragma unroll
                for (int rx = 0; rx < 8; ++rx)
                    #pragma unroll
                    for (int kx = 0; kx < 7; ++kx)
                        acc[ry][rx] = ffma2(rw[rx + kx], w[ky * 7 + kx], acc[ry][rx]);
            }
        }
    }

    float* ob = out + ((size_t)b * NTOK + 1) * CH + c;
    #pragma unroll
    for (int ry = 0; ry < 2; ++ry)
        #pragma unroll
        for (int rx = 0; rx < 8; ++rx) {
            const size_t p = (size_t)(y0 + ry) * HW + (x0 + rx);
            *reinterpret_cast<unsigned long long*>(&ob[p * CH]) = acc[ry][rx];
        }
}

// ---------------------------------------------------------------------------
extern "C" void kernel_launch(void* const* d_in, const int* in_sizes, int n_in,
                              void* d_out, int out_size) {
    const float* x  = (const float*)d_in[0];
    const float* w7 = (const float*)d_in[1];
    const float* b7 = (const float*)d_in[2];
    const float* w5 = (const float*)d_in[3];
    const float* b5 = (const float*)d_in[4];
    const float* w3 = (const float*)d_in[5];
    const float* b3 = (const float*)d_in[6];
    float* out = (float*)d_out;

    ppeg_prep<<<1, CH>>>(w7, b7, w5, b5, w3, b3);
    ppeg_cls<<<16, CH>>>(x, out);
    dim3 grid(4, 16, 16 * 8);
    ppeg_conv<<<grid, 128>>>(x, out);
}

// round 2
// speedup vs baseline: 1.3545x; 1.3545x over previous
#include <cuda_runtime.h>
#include <cstdint>

// PPEG: out[b, 0, c]   = x[b, 0, c]                       (cls token)
//       out[b, 1+p, c] = combined 7x7 depthwise conv of the 64x64 map
// Combined weights: w_eff = w7 + pad(w5) + pad(w3) + identity@center
// Combined bias:    b7 + b5 + b3

#define CH   512
#define HW   64
#define NTOK 4097

__device__ float g_weff[49 * CH];   // [tap][channel]
__device__ float g_bsum[CH];

// packed f32x2 FMA (sm_103a FFMA2 — only reachable via PTX)
__device__ __forceinline__ unsigned long long ffma2(unsigned long long a,
                                                    unsigned long long b,
                                                    unsigned long long c) {
    unsigned long long d;
    asm("fma.rn.f32x2 %0, %1, %2, %3;" : "=l"(d) : "l"(a), "l"(b), "l"(c));
    return d;
}

// ---------------------------------------------------------------------------
// Kernel 1: fold w7/w5/w3/identity. grid=50 (one tap per block, block 49=bias),
// block=512 (one thread per channel). Fully parallel: ~1.5us.
__global__ void ppeg_prep(const float* __restrict__ w7, const float* __restrict__ b7,
                          const float* __restrict__ w5, const float* __restrict__ b5,
                          const float* __restrict__ w3, const float* __restrict__ b3) {
    const int c = threadIdx.x;
    const int t = blockIdx.x;
    if (t == 49) { g_bsum[c] = b7[c] + b5[c] + b3[c]; return; }
    const int ky = t / 7, kx = t % 7;
    float v = w7[c * 49 + t];
    if (ky >= 1 && ky <= 5 && kx >= 1 && kx <= 5)
        v += w5[c * 25 + (ky - 1) * 5 + (kx - 1)];
    if (ky >= 2 && ky <= 4 && kx >= 2 && kx <= 4)
        v += w3[c * 9 + (ky - 2) * 3 + (kx - 2)];
    if (t == 24) v += 1.0f;                       // identity (residual) term
    g_weff[t * CH + c] = v;
}

// ---------------------------------------------------------------------------
// Kernel 2: cls-token passthrough (16 * 512 floats)
__global__ void ppeg_cls(const float* __restrict__ x, float* __restrict__ out) {
    size_t off = (size_t)blockIdx.x * NTOK * CH + threadIdx.x;
    out[off] = x[off];
}

// ---------------------------------------------------------------------------
// Kernel 3: combined 7x7 depthwise conv.
//   lane   = channel pair (64 ch per block) -> 256B coalesced global accesses
//   warp   = 8x2 output pixel subtile per thread
//   block  = 4 warps (2x2) -> 16x4 pixel tile
//   Weights live in SMEM (12.5KB) -> ~110 regs/thread -> 16 warps/SM.
__global__ void __launch_bounds__(128, 4)
ppeg_conv(const float* __restrict__ x, float* __restrict__ out) {
    const int lane = threadIdx.x & 31;
    const int warp = threadIdx.x >> 5;
    const int wx = warp & 1;
    const int wy = warp >> 1;
    const int x0 = blockIdx.x * 16 + wx * 8;   // RX=8 output cols per thread
    const int y0 = blockIdx.y * 4 + wy * 2;    // RY=2 output rows per thread
    const int b  = blockIdx.z >> 3;
    const int cg = blockIdx.z & 7;
    const int cb = cg * 64;                    // channel-group base
    const int c  = cb + lane * 2;

    // Stage this channel group's combined weights + bias into SMEM (coalesced).
    __shared__ __align__(16) float sw[49 * 64];
    __shared__ __align__(16) float sb[64];
    #pragma unroll
    for (int i = threadIdx.x; i < 49 * 64; i += 128) {
        const int t  = i >> 6;
        const int cc = i & 63;
        sw[i] = g_weff[t * CH + cb + cc];
    }
    if (threadIdx.x < 64) sb[threadIdx.x] = g_bsum[cb + threadIdx.x];
    __syncthreads();

    const unsigned long long bias =
        *reinterpret_cast<const unsigned long long*>(&sb[lane * 2]);

    unsigned long long acc[2][8];
    #pragma unroll
    for (int ry = 0; ry < 2; ++ry)
        #pragma unroll
        for (int rx = 0; rx < 8; ++rx)
            acc[ry][rx] = bias;

    const float* xb = x + ((size_t)b * NTOK + 1) * CH + c;
    const float* swp = &sw[lane * 2];

    // Sliding row window: 8 input rows feed the 2 output rows (RY+6).
    #pragma unroll
    for (int riy = 0; riy < 8; ++riy) {
        const int iy = y0 - 3 + riy;
        const bool yok = ((unsigned)iy < (unsigned)HW);
        const float* row = xb + (size_t)iy * HW * CH;

        unsigned long long rw[14];
        #pragma unroll
        for (int i = 0; i < 14; ++i) {
            const int xc = x0 - 3 + i;
            rw[i] = (yok && (unsigned)xc < (unsigned)HW)
                  ? *reinterpret_cast<const unsigned long long*>(&row[(size_t)xc * CH])
                  : 0ULL;
        }

        #pragma unroll
        for (int ky = 0; ky < 7; ++ky) {
            const int ry = riy - ky;          // compile-time after full unroll
            if (ry == 0 || ry == 1) {
                #pragma unroll
                for (int kx = 0; kx < 7; ++kx) {
                    const unsigned long long wk =
                        *reinterpret_cast<const unsigned long long*>(
                            &swp[(ky * 7 + kx) * 64]);
                    #pragma unroll
                    for (int rx = 0; rx < 8; ++rx)
                        acc[ry][rx] = ffma2(rw[rx + kx], wk, acc[ry][rx]);
                }
            }
        }
    }

    float* ob = out + ((size_t)b * NTOK + 1) * CH + c;
    #pragma unroll
    for (int ry = 0; ry < 2; ++ry)
        #pragma unroll
        for (int rx = 0; rx < 8; ++rx) {
            const size_t p = (size_t)(y0 + ry) * HW + (x0 + rx);
            *reinterpret_cast<unsigned long long*>(&ob[p * CH]) = acc[ry][rx];
        }
}

// ---------------------------------------------------------------------------
extern "C" void kernel_launch(void* const* d_in, const int* in_sizes, int n_in,
                              void* d_out, int out_size) {
    const float* x  = (const float*)d_in[0];
    const float* w7 = (const float*)d_in[1];
    const float* b7 = (const float*)d_in[2];
    const float* w5 = (const float*)d_in[3];
    const float* b5 = (const float*)d_in[4];
    const float* w3 = (const float*)d_in[5];
    const float* b3 = (const float*)d_in[6];
    float* out = (float*)d_out;

    ppeg_prep<<<50, CH>>>(w7, b7, w5, b5, w3, b3);
    ppeg_cls<<<16, CH>>>(x, out);
    dim3 grid(4, 16, 16 * 8);
    ppeg_conv<<<grid, 128>>>(x, out);
}